// round 12
// baseline (speedup 1.0000x reference)
#include <cuda_runtime.h>
#include <cstdint>
#include <math.h>

// CropAndResize: x [B,H,W,C=4] fp32, boxes [B,4] (y1,x1,y2,x2 in [0,1]),
// output [B,crop,crop,4] fp32 bilinear.
//
// Lane-pair gather (R8: tl|tr is one contiguous 32B span; even lane loads
// the left float4 column, odd lane the right -> 2 LDG.128 per warp per 16 px
// instead of 4 per 32 px, ~4.5 lines/LDG instead of ~7 -> ~40% fewer L1tex
// replay cycles) combined with R9's division-free decomposition
// (grid = (row, batch), all vertical math blockIdx-uniform). R8's loss was
// two integer divisions per thread, not the pairing itself.

#define TPB 448   // 14 warps x 16 px = 224 px per iteration

__global__ __launch_bounds__(TPB)
void crop_resize_pair2d_kernel(const float* __restrict__ x,
                               const float* __restrict__ boxes,
                               float* __restrict__ out,
                               int H, int W, int crop) {
    const int r = blockIdx.x;          // output row  (uniform)
    const int b = blockIdx.y;          // batch       (uniform)
    const int side = threadIdx.x & 1;  // 0: left col, 1: right col

    const float4 bx = __ldg((const float4*)boxes + b);   // y1,x1,y2,x2
    const float inv = 1.0f / (float)(crop - 1);
    const float hm1 = (float)(H - 1);
    const float wm1 = (float)(W - 1);

    // ---- row-uniform vertical math (uniform pipe) ----
    const float in_y = (bx.x + (float)r * inv * (bx.z - bx.x)) * hm1;
    const bool valid_y = (in_y >= 0.0f) && (in_y <= hm1);
    const int t = min(max((int)in_y, 0), H - 2);
    const float yl = in_y - (float)t;

    const float4* __restrict__ rowT =
        (const float4*)(x) + ((size_t)b * H + t) * W;
    float4* __restrict__ outrow =
        (float4*)(out) + ((size_t)b * crop + r) * crop;

    const float xoff = bx.y * wm1;
    const float xscl = inv * (bx.w - bx.y) * wm1;

    const int pstride = TPB >> 1;      // pixels per iteration

    for (int p = (threadIdx.x >> 1); p < crop; p += pstride) {
        const float in_x = fmaf((float)p, xscl, xoff);
        const bool valid = valid_y && (in_x >= 0.0f) && (in_x <= wm1);

        const int l = min(max((int)in_x, 0), W - 2);
        const float xl = in_x - (float)l;

        const size_t base = (size_t)l + side;   // this lane's column
        const float4 ct = __ldg(rowT + base);        // top
        const float4 cb = __ldg(rowT + base + W);    // bottom

        // vertical lerp (own column)
        float4 v;
        v.x = fmaf(cb.x - ct.x, yl, ct.x);
        v.y = fmaf(cb.y - ct.y, yl, ct.y);
        v.z = fmaf(cb.z - ct.z, yl, ct.z);
        v.w = fmaf(cb.w - ct.w, yl, ct.w);

        // even lane receives odd lane's (right column) result
        float4 vr;
        vr.x = __shfl_down_sync(0xffffffffu, v.x, 1);
        vr.y = __shfl_down_sync(0xffffffffu, v.y, 1);
        vr.z = __shfl_down_sync(0xffffffffu, v.z, 1);
        vr.w = __shfl_down_sync(0xffffffffu, v.w, 1);

        if (side == 0) {
            float4 res = make_float4(0.f, 0.f, 0.f, 0.f);
            if (valid) {
                res.x = fmaf(vr.x - v.x, xl, v.x);
                res.y = fmaf(vr.y - v.y, xl, v.y);
                res.z = fmaf(vr.z - v.z, xl, v.z);
                res.w = fmaf(vr.w - v.w, xl, v.w);
            }
            outrow[p] = res;
        }
    }
}

extern "C" void kernel_launch(void* const* d_in, const int* in_sizes, int n_in,
                              void* d_out, int out_size) {
    const float* x     = (const float*)d_in[0];
    const float* boxes = (const float*)d_in[1];
    float* out = (float*)d_out;

    const int B = in_sizes[1] / 4;          // boxes is [B,4]
    const int C = 4;
    const long long hw = (long long)in_sizes[0] / ((long long)B * C);
    int H = (int)(sqrt((double)hw) + 0.5);
    int W = H;
    const long long cc = (long long)out_size / ((long long)B * C);
    int crop = (int)(sqrt((double)cc) + 0.5);

    dim3 grid(crop, B);
    crop_resize_pair2d_kernel<<<grid, TPB>>>(x, boxes, out, H, W, crop);
}

// round 13
// speedup vs baseline: 1.2243x; 1.2243x over previous
#include <cuda_runtime.h>
#include <cstdint>
#include <math.h>

// CropAndResize: x [B,H,W,C=4] fp32, boxes [B,4] (y1,x1,y2,x2 in [0,1]),
// output [B,crop,crop,4] fp32 bilinear.
//
// R9 direct-gather base (proven optimal SM-side pattern across 12 rounds)
// with two changes:
//  1. Corner gathers use ld.global.nc.L2::256B -> each L2 miss fetches a
//     256B chunk. The gather stream densely covers the source span, so the
//     extra line is ~always useful: DRAM request count ~halves for the
//     same 55MB traffic (dram__cycles_active was only 40% in R1/R9).
//  2. Two output rows per block (448 threads, row split at a warp
//     boundary, division-free) -> balanced SMSPs, half the block churn.

__device__ __forceinline__ float4 ldg_p256(const float4* p) {
    float4 v;
    asm("ld.global.nc.L2::256B.v4.f32 {%0,%1,%2,%3}, [%4];"
        : "=f"(v.x), "=f"(v.y), "=f"(v.z), "=f"(v.w) : "l"(p));
    return v;
}

__global__ __launch_bounds__(512)
void crop_resize_p256_kernel(const float* __restrict__ x,
                             const float* __restrict__ boxes,
                             float* __restrict__ out,
                             int H, int W, int crop) {
    const int half = blockDim.x >> 1;             // multiple of 32
    const int sub  = (threadIdx.x >= half) ? 1 : 0;   // warp-uniform
    const int r    = blockIdx.x * 2 + sub;        // output row (warp-uniform)
    const int b    = blockIdx.y;                  // batch (uniform)
    const int c0   = threadIdx.x - sub * half;

    const float4 bx = __ldg((const float4*)boxes + b);   // y1,x1,y2,x2
    const float inv = 1.0f / (float)(crop - 1);
    const float hm1 = (float)(H - 1);
    const float wm1 = (float)(W - 1);

    if (r >= crop) return;                        // warp-uniform (odd crop)

    // ---- vertical math (warp-uniform) ----
    const float in_y = (bx.x + (float)r * inv * (bx.z - bx.x)) * hm1;
    const bool valid_y = (in_y >= 0.0f) && (in_y <= hm1);
    const int t = min(max((int)in_y, 0), H - 2);
    const float yl = in_y - (float)t;

    const float4* __restrict__ rowT =
        (const float4*)(x) + ((size_t)b * H + t) * W;
    float4* __restrict__ outrow =
        (float4*)(out) + ((size_t)b * crop + r) * crop;

    const float xoff = bx.y * wm1;
    const float xscl = inv * (bx.w - bx.y) * wm1;

    for (int c = c0; c < crop; c += half) {
        const float in_x = fmaf((float)c, xscl, xoff);
        const bool valid = valid_y && (in_x >= 0.0f) && (in_x <= wm1);

        const int l = min(max((int)in_x, 0), W - 2);
        const float xl = in_x - (float)l;

        const float4 tl4 = ldg_p256(rowT + l);
        const float4 tr4 = ldg_p256(rowT + l + 1);
        const float4 bl4 = ldg_p256(rowT + l + W);
        const float4 br4 = ldg_p256(rowT + l + W + 1);

        float4 res = make_float4(0.f, 0.f, 0.f, 0.f);
        if (valid) {
            const float tx0 = fmaf(tr4.x - tl4.x, xl, tl4.x);
            const float ty0 = fmaf(tr4.y - tl4.y, xl, tl4.y);
            const float tz0 = fmaf(tr4.z - tl4.z, xl, tl4.z);
            const float tw0 = fmaf(tr4.w - tl4.w, xl, tl4.w);
            const float bx0 = fmaf(br4.x - bl4.x, xl, bl4.x);
            const float by0 = fmaf(br4.y - bl4.y, xl, bl4.y);
            const float bz0 = fmaf(br4.z - bl4.z, xl, bl4.z);
            const float bw0 = fmaf(br4.w - bl4.w, xl, bl4.w);
            res.x = fmaf(bx0 - tx0, yl, tx0);
            res.y = fmaf(by0 - ty0, yl, ty0);
            res.z = fmaf(bz0 - tz0, yl, tz0);
            res.w = fmaf(bw0 - tw0, yl, tw0);
        }
        outrow[c] = res;
    }
}

extern "C" void kernel_launch(void* const* d_in, const int* in_sizes, int n_in,
                              void* d_out, int out_size) {
    const float* x     = (const float*)d_in[0];
    const float* boxes = (const float*)d_in[1];
    float* out = (float*)d_out;

    const int B = in_sizes[1] / 4;          // boxes is [B,4]
    const int C = 4;
    const long long hw = (long long)in_sizes[0] / ((long long)B * C);
    int H = (int)(sqrt((double)hw) + 0.5);
    int W = H;
    const long long cc = (long long)out_size / ((long long)B * C);
    int crop = (int)(sqrt((double)cc) + 0.5);

    // two rows per block; per-row thread count = multiple of 32 covering crop
    int half = ((crop + 31) / 32) * 32;
    if (half > 256) half = 256;             // column loop handles the rest
    const int tpb = 2 * half;
    dim3 grid((crop + 1) / 2, B);
    crop_resize_p256_kernel<<<grid, tpb>>>(x, boxes, out, H, W, crop);
}